// round 5
// baseline (speedup 1.0000x reference)
#include <cuda_runtime.h>
#include <cstdint>

// ---------------------------------------------------------------------------
// Problem constants
//   x:  (B=32, S=2048, I=256)  fp32
//   h0: (1, 32, 256)   c0: (1, 32, 256)
//   W:  (512, 1024)  rows 0..255 = Wx, rows 256..511 = Wh
//   b:  (1024,)
//   out = concat( hs (32,2048,256), zeros(1,32,256), zeros(1,32,256) )
// ---------------------------------------------------------------------------

#define B_   32
#define S_   2048
#define H_   256
#define N4H  1024
#define RGRID 128   // CTAs in persistent recurrent kernel (<=148 -> all resident)

// Scratch: P[s][b][n] = x[b,s,:] @ Wx + bias   (256 MB)
__device__ float    g_P[(size_t)S_ * B_ * N4H];
// Double-buffered hidden state
__device__ float    g_hbuf[2][B_ * H_];
// Global barrier counter
__device__ unsigned g_bar;

// ---------------------------------------------------------------------------
// Init: reset barrier counter, zero the two trailing output tensors
// ---------------------------------------------------------------------------
__global__ void init_kernel(float* out, int out_size) {
    int i = blockIdx.x * blockDim.x + threadIdx.x;
    if (i == 0) g_bar = 0u;
    const int base = B_ * S_ * H_;            // 16,777,216
    int n = out_size - base;                  // 16,384 (two (1,32,256) zero tensors)
    if (i < n) out[base + i] = 0.0f;
}

// ---------------------------------------------------------------------------
// Kernel 1: P = X @ Wx + bias, written transposed to [s][b][n]
//   A = X reshaped (65536, 256), row r = b*2048 + s
//   BM=128, BN=64, BK=16, 256 threads, 8x4 microtile
// ---------------------------------------------------------------------------
__global__ __launch_bounds__(256) void gemm_xw(const float* __restrict__ X,
                                               const float* __restrict__ W,
                                               const float* __restrict__ bias) {
    __shared__ float As[16][132];   // [k][m], padded (132 ≡ 4 mod 32, 16B-aligned rows)
    __shared__ float Bs[16][68];    // [k][n], padded

    const int bn  = blockIdx.x;          // 0..15   (N tiles of 64)
    const int bm  = blockIdx.y;          // 0..511  (M tiles of 128)
    const int tid = threadIdx.x;
    const int tx  = tid & 15;            // 0..15 -> n
    const int ty  = tid >> 4;            // 0..15 -> m

    const int rowBase = bm * 128;
    const int colBase = bn * 64;

    float acc[8][4];
#pragma unroll
    for (int i = 0; i < 8; i++)
#pragma unroll
        for (int j = 0; j < 4; j++) acc[i][j] = 0.0f;

    for (int k0 = 0; k0 < 256; k0 += 16) {
        // Load A tile (128x16): 512 float4, 2 per thread, store transposed
#pragma unroll
        for (int it = 0; it < 2; it++) {
            int idx = tid + it * 256;          // 0..511
            int m   = idx >> 2;                // 0..127
            int kq  = (idx & 3) << 2;          // 0,4,8,12
            float4 v = *(const float4*)(X + (size_t)(rowBase + m) * 256 + k0 + kq);
            As[kq + 0][m] = v.x;
            As[kq + 1][m] = v.y;
            As[kq + 2][m] = v.z;
            As[kq + 3][m] = v.w;
        }
        // Load B tile (16x64): 256 float4, 1 per thread
        {
            int kk = tid >> 4;                 // 0..15
            int nq = (tid & 15) << 2;          // 0..60
            float4 v = *(const float4*)(W + (size_t)(k0 + kk) * N4H + colBase + nq);
            *(float4*)&Bs[kk][nq] = v;
        }
        __syncthreads();

#pragma unroll
        for (int k = 0; k < 16; k++) {
            float a[8], bb[4];
            *(float4*)&a[0] = *(const float4*)&As[k][ty * 8];
            *(float4*)&a[4] = *(const float4*)&As[k][ty * 8 + 4];
            *(float4*)&bb[0] = *(const float4*)&Bs[k][tx * 4];
#pragma unroll
            for (int i = 0; i < 8; i++)
#pragma unroll
                for (int j = 0; j < 4; j++) acc[i][j] += a[i] * bb[j];
        }
        __syncthreads();
    }

    // Epilogue: add bias, scatter rows to [s][b][n] layout
    float4 bv = *(const float4*)(bias + colBase + tx * 4);
#pragma unroll
    for (int i = 0; i < 8; i++) {
        int r = rowBase + ty * 8 + i;      // r = b*2048 + s
        int bb = r >> 11;
        int ss = r & 2047;
        float4 o;
        o.x = acc[i][0] + bv.x;
        o.y = acc[i][1] + bv.y;
        o.z = acc[i][2] + bv.z;
        o.w = acc[i][3] + bv.w;
        *(float4*)(g_P + ((size_t)(ss * 32 + bb) * N4H + colBase + tx * 4)) = o;
    }
}

// ---------------------------------------------------------------------------
// Kernel 2: persistent recurrent LSTM.
//   128 CTAs x 256 threads. CTA `cta` owns h-columns {2*cta, 2*cta+1}.
//   warp w (0..7): gate g = w&3, half l = w>>2  -> z-column g*256 + 2*cta + l.
//   lane = batch b. Each thread computes one z = dot(h, Wh[:,zcol]) (K=256).
//   Wh slice staged in smem once. h broadcast from global each step.
//   Grid-wide barrier per step via atomic counter + volatile spin.
// ---------------------------------------------------------------------------
__global__ __launch_bounds__(256, 1) void lstm_rec(const float* __restrict__ h0,
                                                   const float* __restrict__ c0,
                                                   const float* __restrict__ W,
                                                   float* __restrict__ out) {
    __shared__ float hs[B_ * 260];     // [b][k], stride 260 (≡4 mod 32 -> conflict-free LDS.128)
    __shared__ float Whs[8 * 256];     // [w][k]: this CTA's 8 Wh columns
    __shared__ float zs[8 * 32];       // [w][b]
    __shared__ float cs[2 * 32];       // [l][b] cell state for the 2 owned columns

    const int tid  = threadIdx.x;
    const int w    = tid >> 5;
    const int lane = tid & 31;
    const int cta  = blockIdx.x;       // 0..127
    const int g    = w & 3;
    const int l    = w >> 2;
    const int zcol = g * 256 + 2 * cta + l;

    // Stage this CTA's Wh columns (rows 256..511 of W) into smem — once.
    for (int k = lane; k < 256; k += 32)
        Whs[w * 256 + k] = W[(size_t)(256 + k) * N4H + zcol];

    // Cell state init for the 2 owned h-columns
    if (tid < 64) {
        int li = tid >> 5;
        int bb = tid & 31;
        cs[tid] = c0[bb * H_ + 2 * cta + li];
    }
    __syncthreads();

    for (int t = 0; t < S_; t++) {
        // ---- broadcast-load h_t into smem (L2-coherent loads) ----
        const float* hsrc = (t == 0) ? h0 : g_hbuf[t & 1];
        for (int idx = tid; idx < B_ * 64; idx += 256) {
            int bb = idx >> 6;
            int kq = (idx & 63) << 2;
            float4 v = __ldcg((const float4*)(hsrc + bb * H_ + kq));
            *(float4*)&hs[bb * 260 + kq] = v;
        }
        __syncthreads();

        // ---- z = tanh( h . Wh[:,zcol] + P[t][b][zcol] ) ----
        float a0 = 0.f, a1 = 0.f, a2 = 0.f, a3 = 0.f;
        const float4* hp = (const float4*)&hs[lane * 260];
        const float4* wp = (const float4*)&Whs[w * 256];
#pragma unroll 8
        for (int kq = 0; kq < 64; kq++) {
            float4 hv = hp[kq];
            float4 wv = wp[kq];
            a0 += hv.x * wv.x;
            a1 += hv.y * wv.y;
            a2 += hv.z * wv.z;
            a3 += hv.w * wv.w;
        }
        float pre = (a0 + a1) + (a2 + a3) + g_P[((size_t)t * 32 + lane) * N4H + zcol];
        zs[w * 32 + lane] = tanhf(pre);
        __syncthreads();

        // ---- gate combine + cell update (warps 0,1 = halves 0,1) ----
        if (w < 2) {
            int li = w;
            int bb = lane;
            float zi = zs[(li * 4 + 0) * 32 + bb];
            float zf = zs[(li * 4 + 1) * 32 + bb];
            float zg = zs[(li * 4 + 2) * 32 + bb];
            float zo = zs[(li * 4 + 3) * 32 + bb];
            float ig = 1.0f / (1.0f + __expf(-zi));
            float fg = 1.0f / (1.0f + __expf(-zf));
            float gg = tanhf(zg);
            float og = 1.0f / (1.0f + __expf(-zo));
            float c  = fg * cs[li * 32 + bb] + ig * gg;
            cs[li * 32 + bb] = c;
            float hn = tanhf(c) * og;
            int col = 2 * cta + li;
            out[((size_t)bb * S_ + t) * H_ + col] = hn;
            g_hbuf[(t + 1) & 1][bb * H_ + col] = hn;
            __threadfence();   // release h writes to GPU scope
        }
        __syncthreads();

        // ---- grid-wide barrier (monotone epoch counter) ----
        if (tid == 0) {
            atomicAdd(&g_bar, 1u);
            unsigned target = (unsigned)(t + 1) * (unsigned)RGRID;
            while (*(volatile unsigned*)&g_bar < target) { }
            __threadfence();   // acquire
        }
        __syncthreads();
    }
}

// ---------------------------------------------------------------------------
extern "C" void kernel_launch(void* const* d_in, const int* in_sizes, int n_in,
                              void* d_out, int out_size) {
    const float* x    = (const float*)d_in[0];
    const float* h0   = (const float*)d_in[1];
    const float* c0   = (const float*)d_in[2];
    const float* W    = (const float*)d_in[3];
    const float* bias = (const float*)d_in[4];
    float* out = (float*)d_out;

    init_kernel<<<64, 256>>>(out, out_size);

    dim3 ggrid(16, 512);
    gemm_xw<<<ggrid, 256>>>(x, W, bias);

    lstm_rec<<<RGRID, 256>>>(h0, c0, W, out);
}

// round 7
// speedup vs baseline: 1.4968x; 1.4968x over previous
#include <cuda_runtime.h>
#include <cstdint>

// ---------------------------------------------------------------------------
// Problem constants
//   x:  (B=32, S=2048, I=256)  fp32
//   h0: (1, 32, 256)   c0: (1, 32, 256)
//   W:  (512, 1024)  rows 0..255 = Wx, rows 256..511 = Wh
//   b:  (1024,)
//   out = concat( hs (32,2048,256), zeros(1,32,256), zeros(1,32,256) )
// ---------------------------------------------------------------------------

#define B_   32
#define S_   2048
#define H_   256
#define N4H  1024

// Scratch: P[b][s][n] = x[b,s,:] @ Wx + bias   (256 MB)
__device__ float    g_P[(size_t)B_ * S_ * N4H];
// Double-buffered hidden state  g_h[buf][b][col]
__device__ float    g_h[2][B_ * H_];
// Per-group barrier counters (16 groups, padded 256B apart)
__device__ unsigned g_ctr[16 * 64];

// ---------------------------------------------------------------------------
// Init: reset barrier counters, zero the two trailing output tensors
// ---------------------------------------------------------------------------
__global__ void init_kernel(float* out, int out_size) {
    int i = blockIdx.x * blockDim.x + threadIdx.x;
    if (i < 16 * 64) g_ctr[i] = 0u;
    const int base = B_ * S_ * H_;            // 16,777,216
    int n = out_size - base;                  // 16,384
    if (i < n) out[base + i] = 0.0f;
}

// ---------------------------------------------------------------------------
// Kernel 1: P = X @ Wx + bias -> g_P[b][s][n]  (natural row-major: row r=b*S+s)
//   BM=128, BN=64, BK=16, 256 threads, 8x4 microtile
// ---------------------------------------------------------------------------
__global__ __launch_bounds__(256) void gemm_xw(const float* __restrict__ X,
                                               const float* __restrict__ W,
                                               const float* __restrict__ bias) {
    __shared__ float As[16][132];
    __shared__ float Bs[16][68];

    const int bn  = blockIdx.x;          // 0..15
    const int bm  = blockIdx.y;          // 0..511
    const int tid = threadIdx.x;
    const int tx  = tid & 15;
    const int ty  = tid >> 4;

    const int rowBase = bm * 128;
    const int colBase = bn * 64;

    float acc[8][4];
#pragma unroll
    for (int i = 0; i < 8; i++)
#pragma unroll
        for (int j = 0; j < 4; j++) acc[i][j] = 0.0f;

    for (int k0 = 0; k0 < 256; k0 += 16) {
#pragma unroll
        for (int it = 0; it < 2; it++) {
            int idx = tid + it * 256;
            int m   = idx >> 2;
            int kq  = (idx & 3) << 2;
            float4 v = *(const float4*)(X + (size_t)(rowBase + m) * 256 + k0 + kq);
            As[kq + 0][m] = v.x;
            As[kq + 1][m] = v.y;
            As[kq + 2][m] = v.z;
            As[kq + 3][m] = v.w;
        }
        {
            int kk = tid >> 4;
            int nq = (tid & 15) << 2;
            float4 v = *(const float4*)(W + (size_t)(k0 + kk) * N4H + colBase + nq);
            *(float4*)&Bs[kk][nq] = v;
        }
        __syncthreads();

#pragma unroll
        for (int k = 0; k < 16; k++) {
            float a[8], bb[4];
            *(float4*)&a[0] = *(const float4*)&As[k][ty * 8];
            *(float4*)&a[4] = *(const float4*)&As[k][ty * 8 + 4];
            *(float4*)&bb[0] = *(const float4*)&Bs[k][tx * 4];
#pragma unroll
            for (int i = 0; i < 8; i++)
#pragma unroll
                for (int j = 0; j < 4; j++) acc[i][j] += a[i] * bb[j];
        }
        __syncthreads();
    }

    float4 bv = *(const float4*)(bias + colBase + tx * 4);
#pragma unroll
    for (int i = 0; i < 8; i++) {
        int r = rowBase + ty * 8 + i;      // r = b*S + s  (row-major -> direct)
        float4 o;
        o.x = acc[i][0] + bv.x;
        o.y = acc[i][1] + bv.y;
        o.z = acc[i][2] + bv.z;
        o.w = acc[i][3] + bv.w;
        *(float4*)(g_P + (size_t)r * N4H + colBase + tx * 4) = o;
    }
}

// ---------------------------------------------------------------------------
// Kernel 2: batch-partitioned persistent recurrent LSTM.
//   128 CTAs = 16 groups x 8. Group grp owns batches {2*grp, 2*grp+1}.
//   CTA j=cta%8 owns h-columns [32j, 32j+32) -> z-cols {g*256 + 32j + c}.
//   128 threads: warp = gate (0..3), lane = c (0..31).
//   Thread computes its z-column for BOTH batches (weight reuse r=2).
//   Wh slice [128 cols][K=256] in smem (pad 260, conflict-free LDS.128).
//   Sync: per-group monotone counter (8 arrivers). No grid-wide barrier.
// ---------------------------------------------------------------------------
#define WS_F   (128 * 260)         // Wh slice floats
#define HS_F   (2 * 260)           // h for 2 batches
#define ZS_F   (8 * 32)            // z[gate][batch][c]
#define CS_F   (2 * 32)            // cell state
#define SMEM_F (WS_F + HS_F + ZS_F + CS_F)

__global__ __launch_bounds__(128, 1) void lstm_rec(const float* __restrict__ h0,
                                                   const float* __restrict__ c0,
                                                   const float* __restrict__ W,
                                                   float* __restrict__ out) {
    extern __shared__ float smem[];
    float* Ws = smem;                 // [col(g*32+c)][k] stride 260
    float* hs = smem + WS_F;          // [bi][k] stride 260
    float* zs = smem + WS_F + HS_F;   // [(g*2+bi)*32 + c]
    float* cs = smem + WS_F + HS_F + ZS_F; // [bi*32 + c]

    const int tid  = threadIdx.x;
    const int g    = tid >> 5;        // gate 0..3
    const int lane = tid & 31;        // c
    const int cta  = blockIdx.x;
    const int grp  = cta >> 3;        // 0..15
    const int j    = cta & 7;         // 0..7
    const int b0   = 2 * grp;
    const int b1   = 2 * grp + 1;
    const int colBase = 32 * j;                 // h-col base of this CTA
    const int zcol    = g * 256 + colBase + lane;

    // ---- stage Wh slice: Ws[gate*32+c][k], global W rows 256..511 ----
    for (int idx = tid; idx < 128 * 256; idx += 128) {
        int k  = idx >> 7;            // 0..255
        int cc = idx & 127;           // [gate(2b)|c(5b)]
        int gg = cc >> 5;
        int c  = cc & 31;
        float v = W[(size_t)(256 + k) * N4H + gg * 256 + colBase + c];
        Ws[cc * 260 + k] = v;
    }
    // cell state init
    if (tid < 64) {
        int bi = tid >> 5;
        int c  = tid & 31;
        cs[bi * 32 + c] = c0[(b0 + bi) * H_ + colBase + c];
    }
    __syncthreads();

    const unsigned ctrSlot = grp * 64;

    for (int t = 0; t < S_; t++) {
        // ---- stage h_t (2 batches x 256) from global/L2 into smem ----
        {
            const float* hsrc = (t == 0) ? h0 : g_h[t & 1];
            int bi = tid >> 6;            // 0..1
            int kq = (tid & 63) << 2;     // 0..252
            float4 v = __ldcg((const float4*)(hsrc + (b0 + bi) * H_ + kq));
            *(float4*)&hs[bi * 260 + kq] = v;
        }
        __syncthreads();

        // ---- P loads (independent of h): issue before dot loop ----
        float pa = __ldcg(&g_P[((size_t)b0 * S_ + t) * N4H + zcol]);
        float pb = __ldcg(&g_P[((size_t)b1 * S_ + t) * N4H + zcol]);

        // ---- dot: z[b] = h[b] . Wh[:,zcol]   (both batches, weight reused)
        float a00 = 0.f, a01 = 0.f, a02 = 0.f, a03 = 0.f;
        float a10 = 0.f, a11 = 0.f, a12 = 0.f, a13 = 0.f;
        const float4* wp  = (const float4*)&Ws[(g * 32 + lane) * 260];
        const float4* hp0 = (const float4*)&hs[0];
        const float4* hp1 = (const float4*)&hs[260];
#pragma unroll 8
        for (int q = 0; q < 64; q++) {
            float4 w  = wp[q];      // strided, conflict-free
            float4 x0 = hp0[q];     // broadcast
            float4 x1 = hp1[q];     // broadcast
            a00 += w.x * x0.x; a01 += w.y * x0.y;
            a02 += w.z * x0.z; a03 += w.w * x0.w;
            a10 += w.x * x1.x; a11 += w.y * x1.y;
            a12 += w.z * x1.z; a13 += w.w * x1.w;
        }
        float pre0 = (a00 + a01) + (a02 + a03) + pa;
        float pre1 = (a10 + a11) + (a12 + a13) + pb;
        zs[(g * 2 + 0) * 32 + lane] = tanhf(pre0);
        zs[(g * 2 + 1) * 32 + lane] = tanhf(pre1);
        __syncthreads();

        // ---- gate combine + cell/h update (64 threads: bi x c) ----
        if (tid < 64) {
            int bi = tid >> 5;
            int c  = tid & 31;
            float zi = zs[(0 * 2 + bi) * 32 + c];
            float zf = zs[(1 * 2 + bi) * 32 + c];
            float zg = zs[(2 * 2 + bi) * 32 + c];
            float zo = zs[(3 * 2 + bi) * 32 + c];
            float ig = 1.0f / (1.0f + __expf(-zi));
            float fg = 1.0f / (1.0f + __expf(-zf));
            float gg = tanhf(zg);
            float og = 1.0f / (1.0f + __expf(-zo));
            float cv = fg * cs[bi * 32 + c] + ig * gg;
            cs[bi * 32 + c] = cv;
            float hn = tanhf(cv) * og;
            int bb  = b0 + bi;
            int col = colBase + c;
            out[((size_t)bb * S_ + t) * H_ + col] = hn;
            g_h[(t + 1) & 1][bb * H_ + col] = hn;
            __threadfence();   // release h writes to GPU scope
        }
        __syncthreads();

        // ---- group-local barrier (8 CTAs, monotone epoch counter) ----
        if (tid == 0) {
            atomicAdd(&g_ctr[ctrSlot], 1u);
            unsigned target = (unsigned)(t + 1) * 8u;
            while (*(volatile unsigned*)&g_ctr[ctrSlot] < target) { }
            __threadfence();   // acquire
        }
        __syncthreads();
    }
}

// ---------------------------------------------------------------------------
extern "C" void kernel_launch(void* const* d_in, const int* in_sizes, int n_in,
                              void* d_out, int out_size) {
    const float* x    = (const float*)d_in[0];
    const float* h0   = (const float*)d_in[1];
    const float* c0   = (const float*)d_in[2];
    const float* W    = (const float*)d_in[3];
    const float* bias = (const float*)d_in[4];
    float* out = (float*)d_out;

    cudaFuncSetAttribute(lstm_rec, cudaFuncAttributeMaxDynamicSharedMemorySize,
                         SMEM_F * (int)sizeof(float));

    init_kernel<<<64, 256>>>(out, out_size);

    dim3 ggrid(16, 512);
    gemm_xw<<<ggrid, 256>>>(x, W, bias);

    lstm_rec<<<128, 128, SMEM_F * sizeof(float)>>>(h0, c0, W, out);
}